// round 13
// baseline (speedup 1.0000x reference)
#include <cuda_runtime.h>
#include <cuda_bf16.h>
#include <cstdint>

// ============================================================
// Persistent-CTA bf16 3-term split HMMA. Grid = 2 CTAs/SM; each CTA loops
// over batches of 4 samples (M=256). Weights staged ONCE per CTA.
// Warp = 32 rows x 64 cols (2 m-tiles). Prepacked W2 hi/lo + ctxW^T.
// ============================================================

#define LDAB 72   // bf16 row stride for B tiles (144 B)
#define BPK_U4 (64 * LDAB * 2 / 16)   // 576 uint4 per tile
#define CWT_STRIDE 52                 // floats; conflict-free LDS.128
#define CWT_F4 ((63 * CWT_STRIDE) / 4)  // 819 float4

__device__ uint4  g_Bhi4[BPK_U4];
__device__ uint4  g_Blo4[BPK_U4];
__device__ float4 g_cwT4[CWT_F4];

__device__ __forceinline__ uint32_t smem_u32(const void* p) {
    uint32_t a;
    asm("{ .reg .u64 t; cvta.to.shared.u64 t, %1; cvt.u32.u64 %0, t; }" : "=r"(a) : "l"(p));
    return a;
}

__device__ __forceinline__ void ldsm4(uint32_t r[4], uint32_t addr) {
    asm volatile("ldmatrix.sync.aligned.m8n8.x4.shared.b16 {%0,%1,%2,%3}, [%4];"
                 : "=r"(r[0]), "=r"(r[1]), "=r"(r[2]), "=r"(r[3]) : "r"(addr));
}

__device__ __forceinline__ void mma16816(float c[4], const uint32_t a[4],
                                          uint32_t b0, uint32_t b1) {
    asm volatile("mma.sync.aligned.m16n8k16.row.col.f32.bf16.bf16.f32 "
                 "{%0,%1,%2,%3}, {%4,%5,%6,%7}, {%8,%9}, {%0,%1,%2,%3};"
                 : "+f"(c[0]), "+f"(c[1]), "+f"(c[2]), "+f"(c[3])
                 : "r"(a[0]), "r"(a[1]), "r"(a[2]), "r"(a[3]), "r"(b0), "r"(b1));
}

__device__ __forceinline__ void split_pack(float a, float b, uint32_t& hi, uint32_t& lo) {
    uint32_t h;
    asm("cvt.rn.bf16x2.f32 %0, %1, %2;" : "=r"(h) : "f"(b), "f"(a));
    float fa = __uint_as_float(h << 16);
    float fb = __uint_as_float(h & 0xffff0000u);
    uint32_t l;
    asm("cvt.rn.bf16x2.f32 %0, %1, %2;" : "=r"(l) : "f"(b - fb), "f"(a - fa));
    hi = h; lo = l;
}

// triu(9) index tables
__constant__ unsigned char c_iu_i[45] = {
    0,0,0,0,0,0,0,0,0, 1,1,1,1,1,1,1,1, 2,2,2,2,2,2,2,
    3,3,3,3,3,3, 4,4,4,4,4, 5,5,5,5, 6,6,6, 7,7, 8};
__constant__ unsigned char c_iu_j[45] = {
    0,1,2,3,4,5,6,7,8, 1,2,3,4,5,6,7,8, 2,3,4,5,6,7,8,
    3,4,5,6,7,8, 4,5,6,7,8, 5,6,7,8, 6,7,8, 7,8, 8};

// float misc region offsets (float4-critical bases % 4 == 0)
#define F_CW   0       // 3276 (63 x 52)
#define F_W1   3276    // 128
#define F_B1   3404    // 64
#define F_B2   3468    // 64
#define F_W3   3532    // 128
#define F_GW   3660    // 49
#define F_GB   3709    // 7
#define F_CB   3716    // 63
#define F_B3   3779    // 2
#define F_X    3784    // 4*63 = 252
#define F_Y    4036    // 252
#define F_ADJ  4288    // 4*81 = 324
#define F_D    4612    // 36
#define F_CTX  4648    // 4*48 = 192 (stride 48, zero padded)
#define F_ZP   4840    // 256
#define F_CP   5096    // 256
#define F_TOTAL 5352

// ---- one-time prepack ----
__global__ void prepack_kernel(const float* __restrict__ W2,
                               const float* __restrict__ ctxW) {
    int i = blockIdx.x * blockDim.x + threadIdx.x;
    if (i < 64 * LDAB) {
        int n = i / LDAB, k = i % LDAB;
        __nv_bfloat16 hi = __float2bfloat16(0.f);
        __nv_bfloat16 lo = hi;
        if (k < 64) {
            float w = W2[n * 64 + k];
            hi = __float2bfloat16(w);
            lo = __float2bfloat16(w - __bfloat162float(hi));
        }
        reinterpret_cast<__nv_bfloat16*>(g_Bhi4)[i] = hi;
        reinterpret_cast<__nv_bfloat16*>(g_Blo4)[i] = lo;
    }
    if (i < 63 * CWT_STRIDE) {
        int g = i / CWT_STRIDE, col = i % CWT_STRIDE;
        reinterpret_cast<float*>(g_cwT4)[i] = (col < 45) ? ctxW[col * 63 + g] : 0.f;
    }
}

__global__ __launch_bounds__(256, 2)
void car_mma9_kernel(const float* __restrict__ x,      // (B,1,9,7)
                     const int*   __restrict__ adj,    // (B,45)
                     const float* __restrict__ ctx,    // (B,1,9,5)
                     const float* __restrict__ gcnW,   // (7,7)
                     const float* __restrict__ gcnB,   // (7,)
                     const float* __restrict__ ctxB,   // (63,)
                     const float* __restrict__ W1,     // (64,2)
                     const float* __restrict__ b1,     // (64,)
                     const float* __restrict__ b2,     // (64,)
                     const float* __restrict__ W3,     // (2,64)
                     const float* __restrict__ b3,     // (2,)
                     float* __restrict__ out,          // (B,2,9,7)
                     int Bn, int nBatch)
{
    __shared__ __align__(16) __nv_bfloat16 sBhi[64 * LDAB];
    __shared__ __align__(16) __nv_bfloat16 sBlo[64 * LDAB];
    __shared__ __align__(16) float sF[F_TOTAL];

    const int tid  = threadIdx.x;
    const int wid  = tid >> 5;
    const int lane = tid & 31;

    // ---- weights staged ONCE per persistent CTA ----
    {
        uint4* dh = reinterpret_cast<uint4*>(sBhi);
        uint4* dl = reinterpret_cast<uint4*>(sBlo);
        #pragma unroll
        for (int i = tid; i < BPK_U4; i += 256) { dh[i] = g_Bhi4[i]; dl[i] = g_Blo4[i]; }
        float4* d4 = reinterpret_cast<float4*>(sF + F_CW);
        for (int i = tid; i < CWT_F4; i += 256) d4[i] = g_cwT4[i];
    }
    if (tid < 32)                  reinterpret_cast<float4*>(sF + F_W1)[tid]      = reinterpret_cast<const float4*>(W1)[tid];
    else if (tid < 64)             reinterpret_cast<float4*>(sF + F_W3)[tid - 32] = reinterpret_cast<const float4*>(W3)[tid - 32];
    else if (tid < 80)             reinterpret_cast<float4*>(sF + F_B1)[tid - 64] = reinterpret_cast<const float4*>(b1)[tid - 64];
    else if (tid < 96)             reinterpret_cast<float4*>(sF + F_B2)[tid - 80] = reinterpret_cast<const float4*>(b2)[tid - 80];
    else if (tid < 96 + 49)        sF[F_GW + tid - 96] = gcnW[tid - 96];
    else if (tid < 145 + 7)        sF[F_GB + tid - 145] = gcnB[tid - 145];
    else if (tid < 152 + 63)       sF[F_CB + tid - 152] = ctxB[tid - 152];
    else if (tid < 215 + 2)        sF[F_B3 + tid - 215] = b3[tid - 215];

    // invariant per-thread constants
    const int grp = tid >> 6;        // 0..3 (staging sample slot)
    const int g64 = tid & 63;
    const int l4  = lane >> 2;
    const int lm4 = lane & 3;
    const int r0  = wid * 32 + l4;   // rows r0+8e, e=0..3
    const uint32_t sub = (uint32_t)(lane >> 3);
    const uint32_t j7  = (uint32_t)(lane & 7);
    const uint32_t bOff = ((sub >> 1) * 8 + j7) * (LDAB * 2) + (sub & 1) * 16;
    const uint32_t bHiBase = smem_u32(sBhi) + bOff;
    const uint32_t bLoBase = smem_u32(sBlo) + bOff;

    for (int batch = blockIdx.x; batch < nBatch; batch += gridDim.x) {
        const int sBase = batch * 4;

        // ---- staging: 4 samples ----
        {
            const int sG = sBase + grp;
            const bool svalid = (sG < Bn);
            sF[F_ADJ + grp * 81 + g64] = 0.f;
            if (g64 < 17) sF[F_ADJ + grp * 81 + 64 + g64] = 0.f;
            if (g64 < 63) sF[F_X + grp * 63 + g64] = svalid ? x[sG * 63 + g64] : 0.f;
            if (g64 < 48) sF[F_CTX + grp * 48 + g64] =
                (g64 < 45 && svalid) ? ctx[sG * 45 + g64] : 0.f;
            __syncthreads();

            // adjacency fill + y = x @ gcnW
            if (svalid && g64 < 45) {
                int i = c_iu_i[g64], j = c_iu_j[g64];
                sF[F_ADJ + grp * 81 + i * 9 + j] = (adj[sG * 45 + g64] > 0) ? 1.f : 0.f;
            }
            if (g64 < 63) {
                int n = g64 / 7, f = g64 % 7;
                float acc = 0.f;
                #pragma unroll
                for (int k = 0; k < 7; ++k)
                    acc = fmaf(sF[F_X + grp * 63 + n * 7 + k], sF[F_GW + k * 7 + f], acc);
                sF[F_Y + grp * 63 + g64] = acc;
            }
            __syncthreads();

            // diag=1, degree norm
            if (g64 < 9) {
                sF[F_ADJ + grp * 81 + g64 * 9 + g64] = 1.f;
                float rs = 0.f;
                #pragma unroll
                for (int m = 0; m < 9; ++m) rs += sF[F_ADJ + grp * 81 + g64 * 9 + m];
                sF[F_D + grp * 9 + g64] = rsqrtf(fmaxf(rs, 1.f));
            }
            __syncthreads();
        }

        // ---- per-row zp AND cp (one row per thread) ----
        {
            const int row = tid;
            const int sl  = row >> 6;
            const int g   = row & 63;
            const bool pv = (g < 63) && (sBase + sl < Bn);
            float c = 0.f, z = 0.f;
            if (pv) {
                const float* cw = sF + F_CW + g * CWT_STRIDE;
                const float* cx = sF + F_CTX + sl * 48;
                float a0 = 0.f, a1 = 0.f, a2 = 0.f, a3 = 0.f;
                #pragma unroll
                for (int i = 0; i < 12; ++i) {
                    const float4 w = *reinterpret_cast<const float4*>(cw + i * 4);
                    const float4 v = *reinterpret_cast<const float4*>(cx + i * 4);
                    a0 = fmaf(v.x, w.x, a0);
                    a1 = fmaf(v.y, w.y, a1);
                    a2 = fmaf(v.z, w.z, a2);
                    a3 = fmaf(v.w, w.w, a3);
                }
                c = fmaxf(sF[F_CB + g] + ((a0 + a1) + (a2 + a3)), 0.f);

                const int n = g / 7, f = g % 7;
                float acc = 0.f;
                #pragma unroll
                for (int m = 0; m < 9; ++m)
                    acc = fmaf(sF[F_ADJ + sl * 81 + n * 9 + m] * sF[F_D + sl * 9 + m],
                               sF[F_Y + sl * 63 + m * 7 + f], acc);
                z = fmaf(acc, sF[F_D + sl * 9 + n], sF[F_GB + f]);
            }
            sF[F_CP + row] = c;
            sF[F_ZP + row] = z;
        }
        __syncthreads();

        // ---- fetch 4 rows' (zp, cp) ----
        float zp[4], cp[4];
        #pragma unroll
        for (int e = 0; e < 4; ++e) {
            zp[e] = sF[F_ZP + r0 + 8 * e];
            cp[e] = sF[F_CP + r0 + 8 * e];
        }

        // ---- k-loop: 2 m-tiles, A in registers, HMMA ----
        float C[2][8][4];
        #pragma unroll
        for (int m = 0; m < 2; ++m)
            #pragma unroll
            for (int n = 0; n < 8; ++n)
                #pragma unroll
                for (int q = 0; q < 4; ++q) C[m][n][q] = 0.f;

        #pragma unroll
        for (int ks = 0; ks < 4; ++ks) {
            uint32_t Ahi[2][4], Alo[2][4];
            const int cb = lm4 * 2 + ks * 16;
            #pragma unroll
            for (int p = 0; p < 2; ++p) {
                const int c = cb + p * 8;
                const float4 w4 = *reinterpret_cast<const float4*>(sF + F_W1 + 2 * c);
                const float2 bb = *reinterpret_cast<const float2*>(sF + F_B1 + c);
                #pragma unroll
                for (int m = 0; m < 2; ++m) {
                    #pragma unroll
                    for (int e = 0; e < 2; ++e) {
                        const int r = 2 * m + e;
                        float v0 = fmaxf(fmaf(zp[r], w4.x, fmaf(cp[r], w4.y, bb.x)), 0.f);
                        float v1 = fmaxf(fmaf(zp[r], w4.z, fmaf(cp[r], w4.w, bb.y)), 0.f);
                        split_pack(v0, v1, Ahi[m][p * 2 + e], Alo[m][p * 2 + e]);
                    }
                }
            }

            const uint32_t kB = (uint32_t)ks * 32;
            #pragma unroll
            for (int nh = 0; nh < 2; ++nh) {
                uint32_t bh[2][4], bl[2][4];
                ldsm4(bh[0], bHiBase + (uint32_t)(nh * 32)      * (LDAB * 2) + kB);
                ldsm4(bh[1], bHiBase + (uint32_t)(nh * 32 + 16) * (LDAB * 2) + kB);
                ldsm4(bl[0], bLoBase + (uint32_t)(nh * 32)      * (LDAB * 2) + kB);
                ldsm4(bl[1], bLoBase + (uint32_t)(nh * 32 + 16) * (LDAB * 2) + kB);
                #pragma unroll
                for (int t = 0; t < 4; ++t) {
                    const int nt = nh * 4 + t;
                    const uint32_t b0h = bh[t >> 1][(t & 1) * 2];
                    const uint32_t b1h = bh[t >> 1][(t & 1) * 2 + 1];
                    const uint32_t b0l = bl[t >> 1][(t & 1) * 2];
                    const uint32_t b1l = bl[t >> 1][(t & 1) * 2 + 1];
                    #pragma unroll
                    for (int m = 0; m < 2; ++m) {
                        mma16816(C[m][nt], Ahi[m], b0h, b1h);   // hi*hi
                        mma16816(C[m][nt], Ahi[m], b0l, b1l);   // hi*lo
                        mma16816(C[m][nt], Alo[m], b0h, b1h);   // lo*hi
                    }
                }
            }
        }

        // ---- epilogue per m-tile ----
        float o[2][2][2];
        #pragma unroll
        for (int m = 0; m < 2; ++m)
            #pragma unroll
            for (int e = 0; e < 2; ++e) { o[m][e][0] = 0.f; o[m][e][1] = 0.f; }

        #pragma unroll
        for (int nt = 0; nt < 8; ++nt) {
            const int cc = nt * 8 + lm4 * 2;
            const float2 b2v = *reinterpret_cast<const float2*>(sF + F_B2 + cc);
            const float2 w3a = *reinterpret_cast<const float2*>(sF + F_W3 + cc);
            const float2 w3b = *reinterpret_cast<const float2*>(sF + F_W3 + 64 + cc);
            #pragma unroll
            for (int m = 0; m < 2; ++m) {
                float h0 = fmaxf(C[m][nt][0] + b2v.x, 0.f);
                float h1 = fmaxf(C[m][nt][1] + b2v.y, 0.f);
                o[m][0][0] = fmaf(w3a.x, h0, fmaf(w3a.y, h1, o[m][0][0]));
                o[m][0][1] = fmaf(w3b.x, h0, fmaf(w3b.y, h1, o[m][0][1]));
                h0 = fmaxf(C[m][nt][2] + b2v.x, 0.f);
                h1 = fmaxf(C[m][nt][3] + b2v.y, 0.f);
                o[m][1][0] = fmaf(w3a.x, h0, fmaf(w3a.y, h1, o[m][1][0]));
                o[m][1][1] = fmaf(w3b.x, h0, fmaf(w3b.y, h1, o[m][1][1]));
            }
        }
        #pragma unroll
        for (int m = 0; m < 2; ++m)
            #pragma unroll
            for (int e = 0; e < 2; ++e)
                #pragma unroll
                for (int ch = 0; ch < 2; ++ch) {
                    o[m][e][ch] += __shfl_xor_sync(0xffffffffu, o[m][e][ch], 1);
                    o[m][e][ch] += __shfl_xor_sync(0xffffffffu, o[m][e][ch], 2);
                }

        if (lm4 == 0) {
            const float bb30 = sF[F_B3 + 0], bb31 = sF[F_B3 + 1];
            #pragma unroll
            for (int m = 0; m < 2; ++m)
                #pragma unroll
                for (int e = 0; e < 2; ++e) {
                    const int row = r0 + m * 16 + e * 8;
                    const int sl  = row >> 6;
                    const int g   = row & 63;
                    const int sO  = sBase + sl;
                    if (g < 63 && sO < Bn) {
                        out[sO * 126 + g]      = o[m][e][0] + bb30;
                        out[sO * 126 + 63 + g] = o[m][e][1] + bb31;
                    }
                }
        }
    }
}

extern "C" void kernel_launch(void* const* d_in, const int* in_sizes, int n_in,
                              void* d_out, int out_size) {
    const float* x    = (const float*)d_in[0];
    const int*   adj  = (const int*)  d_in[1];
    const float* ctx  = (const float*)d_in[2];
    const float* gcnW = (const float*)d_in[3];
    const float* gcnB = (const float*)d_in[4];
    const float* ctxW = (const float*)d_in[5];
    const float* ctxB = (const float*)d_in[6];
    const float* W1   = (const float*)d_in[7];
    const float* b1   = (const float*)d_in[8];
    const float* W2   = (const float*)d_in[9];
    const float* b2   = (const float*)d_in[10];
    const float* W3   = (const float*)d_in[11];
    const float* b3   = (const float*)d_in[12];
    float* outp = (float*)d_out;

    prepack_kernel<<<18, 256>>>(W2, ctxW);

    int Bn = in_sizes[0] / 63;
    int nBatch = (Bn + 3) / 4;
    int grid = 304;                       // 2 persistent CTAs per SM (152 SMs)
    if (grid > nBatch) grid = nBatch;
    car_mma9_kernel<<<grid, 256>>>(x, adj, ctx, gcnW, gcnB, ctxB,
                                   W1, b1, b2, W3, b3, outp, Bn, nBatch);
}

// round 14
// speedup vs baseline: 1.1976x; 1.1976x over previous
#include <cuda_runtime.h>
#include <cuda_fp16.h>
#include <cstdint>

// ============================================================
// fp16 2-term split HMMA (A = hi+lo fp16, B = fp16(W2) single tile).
// D = (ahi+alo)*whi  == exact-A x fp16-quantized weights (rel err ~2.8e-4).
// CTA = 256 thr, 4 samples (M=256), warp = 32 rows x 64 cols (2 m-tiles).
// Prepacked W2(fp16) + transposed ctxW. R12 structure (non-persistent).
// ============================================================

#define LDAB 72   // fp16 row stride for B tile (144 B)
#define BPK_U4 (64 * LDAB * 2 / 16)   // 576 uint4 for the single B tile
#define CWT_STRIDE 52                 // floats; conflict-free LDS.128
#define CWT_F4 ((63 * CWT_STRIDE) / 4)  // 819 float4

__device__ uint4  g_Bhi4[BPK_U4];
__device__ float4 g_cwT4[CWT_F4];

__device__ __forceinline__ uint32_t smem_u32(const void* p) {
    uint32_t a;
    asm("{ .reg .u64 t; cvta.to.shared.u64 t, %1; cvt.u32.u64 %0, t; }" : "=r"(a) : "l"(p));
    return a;
}

__device__ __forceinline__ void ldsm4(uint32_t r[4], uint32_t addr) {
    asm volatile("ldmatrix.sync.aligned.m8n8.x4.shared.b16 {%0,%1,%2,%3}, [%4];"
                 : "=r"(r[0]), "=r"(r[1]), "=r"(r[2]), "=r"(r[3]) : "r"(addr));
}

__device__ __forceinline__ void mma16816(float c[4], const uint32_t a[4],
                                          uint32_t b0, uint32_t b1) {
    asm volatile("mma.sync.aligned.m16n8k16.row.col.f32.f16.f16.f32 "
                 "{%0,%1,%2,%3}, {%4,%5,%6,%7}, {%8,%9}, {%0,%1,%2,%3};"
                 : "+f"(c[0]), "+f"(c[1]), "+f"(c[2]), "+f"(c[3])
                 : "r"(a[0]), "r"(a[1]), "r"(a[2]), "r"(a[3]), "r"(b0), "r"(b1));
}

// fp16 hi/lo split: hi = {f16(a) lo-half, f16(b) hi-half}, lo = residuals
__device__ __forceinline__ void split_pack(float a, float b, uint32_t& hi, uint32_t& lo) {
    __half2 h = __floats2half2_rn(a, b);     // x=a (low), y=b (high)
    float2 f = __half22float2(h);
    __half2 l = __floats2half2_rn(a - f.x, b - f.y);
    hi = *reinterpret_cast<uint32_t*>(&h);
    lo = *reinterpret_cast<uint32_t*>(&l);
}

// triu(9) index tables
__constant__ unsigned char c_iu_i[45] = {
    0,0,0,0,0,0,0,0,0, 1,1,1,1,1,1,1,1, 2,2,2,2,2,2,2,
    3,3,3,3,3,3, 4,4,4,4,4, 5,5,5,5, 6,6,6, 7,7, 8};
__constant__ unsigned char c_iu_j[45] = {
    0,1,2,3,4,5,6,7,8, 1,2,3,4,5,6,7,8, 2,3,4,5,6,7,8,
    3,4,5,6,7,8, 4,5,6,7,8, 5,6,7,8, 6,7,8, 7,8, 8};

// float misc region offsets (float4-critical bases % 4 == 0)
#define F_CW   0       // 3276 (63 x 52)
#define F_W1   3276    // 128
#define F_B1   3404    // 64
#define F_B2   3468    // 64
#define F_W3   3532    // 128
#define F_GW   3660    // 49
#define F_GB   3709    // 7
#define F_CB   3716    // 63
#define F_B3   3779    // 2
#define F_X    3784    // 4*63 = 252
#define F_Y    4036    // 252
#define F_ADJ  4288    // 4*81 = 324
#define F_D    4612    // 36
#define F_CTX  4648    // 4*48 = 192 (stride 48, zero padded)
#define F_ZP   4840    // 256
#define F_CP   5096    // 256
#define F_TOTAL 5352

// ---- one-time prepack: W2 -> fp16 [64][72]; ctxW -> transposed [63][52] ----
__global__ void prepack_kernel(const float* __restrict__ W2,
                               const float* __restrict__ ctxW) {
    int i = blockIdx.x * blockDim.x + threadIdx.x;
    if (i < 64 * LDAB) {
        int n = i / LDAB, k = i % LDAB;
        __half hi = __float2half(0.f);
        if (k < 64) hi = __float2half(W2[n * 64 + k]);
        reinterpret_cast<__half*>(g_Bhi4)[i] = hi;
    }
    if (i < 63 * CWT_STRIDE) {
        int g = i / CWT_STRIDE, col = i % CWT_STRIDE;
        reinterpret_cast<float*>(g_cwT4)[i] = (col < 45) ? ctxW[col * 63 + g] : 0.f;
    }
}

__global__ __launch_bounds__(256, 2)
void car_mma10_kernel(const float* __restrict__ x,      // (B,1,9,7)
                      const int*   __restrict__ adj,    // (B,45)
                      const float* __restrict__ ctx,    // (B,1,9,5)
                      const float* __restrict__ gcnW,   // (7,7)
                      const float* __restrict__ gcnB,   // (7,)
                      const float* __restrict__ ctxB,   // (63,)
                      const float* __restrict__ W1,     // (64,2)
                      const float* __restrict__ b1,     // (64,)
                      const float* __restrict__ b2,     // (64,)
                      const float* __restrict__ W3,     // (2,64)
                      const float* __restrict__ b3,     // (2,)
                      float* __restrict__ out,          // (B,2,9,7)
                      int Bn)
{
    __shared__ __align__(16) __half sBhi[64 * LDAB];
    __shared__ __align__(16) float sF[F_TOTAL];

    const int tid  = threadIdx.x;
    const int wid  = tid >> 5;
    const int lane = tid & 31;

    // ---- phase 1: bulk copies of prepacked weights ----
    {
        uint4* dh = reinterpret_cast<uint4*>(sBhi);
        #pragma unroll
        for (int i = tid; i < BPK_U4; i += 256) dh[i] = g_Bhi4[i];
        float4* d4 = reinterpret_cast<float4*>(sF + F_CW);
        for (int i = tid; i < CWT_F4; i += 256) d4[i] = g_cwT4[i];
    }
    if (tid < 32)                  reinterpret_cast<float4*>(sF + F_W1)[tid]      = reinterpret_cast<const float4*>(W1)[tid];
    else if (tid < 64)             reinterpret_cast<float4*>(sF + F_W3)[tid - 32] = reinterpret_cast<const float4*>(W3)[tid - 32];
    else if (tid < 80)             reinterpret_cast<float4*>(sF + F_B1)[tid - 64] = reinterpret_cast<const float4*>(b1)[tid - 64];
    else if (tid < 96)             reinterpret_cast<float4*>(sF + F_B2)[tid - 80] = reinterpret_cast<const float4*>(b2)[tid - 80];
    else if (tid < 96 + 49)        sF[F_GW + tid - 96] = gcnW[tid - 96];
    else if (tid < 145 + 7)        sF[F_GB + tid - 145] = gcnB[tid - 145];
    else if (tid < 152 + 63)       sF[F_CB + tid - 152] = ctxB[tid - 152];
    else if (tid < 215 + 2)        sF[F_B3 + tid - 215] = b3[tid - 215];

    // per-sample staging: 4 samples / CTA
    const int grp = tid >> 6;        // 0..3
    const int g64 = tid & 63;
    const int sG  = blockIdx.x * 4 + grp;
    const bool svalid = (sG < Bn);
    sF[F_ADJ + grp * 81 + g64] = 0.f;
    if (g64 < 17) sF[F_ADJ + grp * 81 + 64 + g64] = 0.f;
    if (g64 < 63) sF[F_X + grp * 63 + g64] = svalid ? x[sG * 63 + g64] : 0.f;
    if (g64 < 48) sF[F_CTX + grp * 48 + g64] =
        (g64 < 45 && svalid) ? ctx[sG * 45 + g64] : 0.f;
    __syncthreads();

    // ---- phase 2: adjacency fill + y = x @ gcnW ----
    if (svalid && g64 < 45) {
        int i = c_iu_i[g64], j = c_iu_j[g64];
        sF[F_ADJ + grp * 81 + i * 9 + j] = (adj[sG * 45 + g64] > 0) ? 1.f : 0.f;
    }
    if (g64 < 63) {
        int n = g64 / 7, f = g64 % 7;
        float acc = 0.f;
        #pragma unroll
        for (int k = 0; k < 7; ++k)
            acc = fmaf(sF[F_X + grp * 63 + n * 7 + k], sF[F_GW + k * 7 + f], acc);
        sF[F_Y + grp * 63 + g64] = acc;
    }
    __syncthreads();

    // ---- phase 3: diag=1, degree norm ----
    if (g64 < 9) {
        sF[F_ADJ + grp * 81 + g64 * 9 + g64] = 1.f;
        float rs = 0.f;
        #pragma unroll
        for (int m = 0; m < 9; ++m) rs += sF[F_ADJ + grp * 81 + g64 * 9 + m];
        sF[F_D + grp * 9 + g64] = rsqrtf(fmaxf(rs, 1.f));
    }
    __syncthreads();

    // ---- phase 4a: per-row zp AND cp (one row per thread, 256 rows) ----
    {
        const int row = tid;
        const int sl  = row >> 6;
        const int g   = row & 63;
        const bool pv = (g < 63) && (blockIdx.x * 4 + sl < Bn);
        float c = 0.f, z = 0.f;
        if (pv) {
            const float* cw = sF + F_CW + g * CWT_STRIDE;
            const float* cx = sF + F_CTX + sl * 48;
            float a0 = 0.f, a1 = 0.f, a2 = 0.f, a3 = 0.f;
            #pragma unroll
            for (int i = 0; i < 12; ++i) {
                const float4 w = *reinterpret_cast<const float4*>(cw + i * 4);
                const float4 v = *reinterpret_cast<const float4*>(cx + i * 4);
                a0 = fmaf(v.x, w.x, a0);
                a1 = fmaf(v.y, w.y, a1);
                a2 = fmaf(v.z, w.z, a2);
                a3 = fmaf(v.w, w.w, a3);
            }
            c = fmaxf(sF[F_CB + g] + ((a0 + a1) + (a2 + a3)), 0.f);

            const int n = g / 7, f = g % 7;
            float acc = 0.f;
            #pragma unroll
            for (int m = 0; m < 9; ++m)
                acc = fmaf(sF[F_ADJ + sl * 81 + n * 9 + m] * sF[F_D + sl * 9 + m],
                           sF[F_Y + sl * 63 + m * 7 + f], acc);
            z = fmaf(acc, sF[F_D + sl * 9 + n], sF[F_GB + f]);
        }
        sF[F_CP + row] = c;
        sF[F_ZP + row] = z;
    }
    __syncthreads();

    // ---- phase 4b: lanes fetch their 4 rows' (zp, cp) ----
    const int l4  = lane >> 2;
    const int lm4 = lane & 3;
    const int r0  = wid * 32 + l4;     // rows r0+8e, e=0..3 (m-tile = e>>1)

    float zp[4], cp[4];
    #pragma unroll
    for (int e = 0; e < 4; ++e) {
        zp[e] = sF[F_ZP + r0 + 8 * e];
        cp[e] = sF[F_CP + r0 + 8 * e];
    }

    // ---- phase 5: k-loop, 2 m-tiles, fp16 2-term split ----
    float C[2][8][4];
    #pragma unroll
    for (int m = 0; m < 2; ++m)
        #pragma unroll
        for (int n = 0; n < 8; ++n)
            #pragma unroll
            for (int q = 0; q < 4; ++q) C[m][n][q] = 0.f;

    const uint32_t sub = (uint32_t)(lane >> 3);
    const uint32_t j7  = (uint32_t)(lane & 7);
    const uint32_t bOff = ((sub >> 1) * 8 + j7) * (LDAB * 2) + (sub & 1) * 16;
    const uint32_t bHiBase = smem_u32(sBhi) + bOff;

    #pragma unroll
    for (int ks = 0; ks < 4; ++ks) {
        uint32_t Ahi[2][4], Alo[2][4];
        const int cb = lm4 * 2 + ks * 16;
        #pragma unroll
        for (int p = 0; p < 2; ++p) {
            const int c = cb + p * 8;
            const float4 w4 = *reinterpret_cast<const float4*>(sF + F_W1 + 2 * c);
            const float2 bb = *reinterpret_cast<const float2*>(sF + F_B1 + c);
            #pragma unroll
            for (int m = 0; m < 2; ++m) {
                #pragma unroll
                for (int e = 0; e < 2; ++e) {
                    const int r = 2 * m + e;
                    float v0 = fmaxf(fmaf(zp[r], w4.x, fmaf(cp[r], w4.y, bb.x)), 0.f);
                    float v1 = fmaxf(fmaf(zp[r], w4.z, fmaf(cp[r], w4.w, bb.y)), 0.f);
                    split_pack(v0, v1, Ahi[m][p * 2 + e], Alo[m][p * 2 + e]);
                }
            }
        }

        const uint32_t kB = (uint32_t)ks * 32;  // 16 fp16 = 32 bytes
        #pragma unroll
        for (int nh = 0; nh < 2; ++nh) {
            uint32_t bh[2][4];
            ldsm4(bh[0], bHiBase + (uint32_t)(nh * 32)      * (LDAB * 2) + kB);
            ldsm4(bh[1], bHiBase + (uint32_t)(nh * 32 + 16) * (LDAB * 2) + kB);
            #pragma unroll
            for (int t = 0; t < 4; ++t) {
                const int nt = nh * 4 + t;
                const uint32_t b0h = bh[t >> 1][(t & 1) * 2];
                const uint32_t b1h = bh[t >> 1][(t & 1) * 2 + 1];
                #pragma unroll
                for (int m = 0; m < 2; ++m) {
                    mma16816(C[m][nt], Ahi[m], b0h, b1h);   // hi * W
                    mma16816(C[m][nt], Alo[m], b0h, b1h);   // lo * W
                }
            }
        }
    }

    // ---- phase 6: in-register epilogue per m-tile ----
    float o[2][2][2];   // [m][e][ch]
    #pragma unroll
    for (int m = 0; m < 2; ++m)
        #pragma unroll
        for (int e = 0; e < 2; ++e) { o[m][e][0] = 0.f; o[m][e][1] = 0.f; }

    #pragma unroll
    for (int nt = 0; nt < 8; ++nt) {
        const int cc = nt * 8 + lm4 * 2;
        const float2 b2v = *reinterpret_cast<const float2*>(sF + F_B2 + cc);
        const float2 w3a = *reinterpret_cast<const float2*>(sF + F_W3 + cc);
        const float2 w3b = *reinterpret_cast<const float2*>(sF + F_W3 + 64 + cc);
        #pragma unroll
        for (int m = 0; m < 2; ++m) {
            float h0 = fmaxf(C[m][nt][0] + b2v.x, 0.f);
            float h1 = fmaxf(C[m][nt][1] + b2v.y, 0.f);
            o[m][0][0] = fmaf(w3a.x, h0, fmaf(w3a.y, h1, o[m][0][0]));
            o[m][0][1] = fmaf(w3b.x, h0, fmaf(w3b.y, h1, o[m][0][1]));
            h0 = fmaxf(C[m][nt][2] + b2v.x, 0.f);
            h1 = fmaxf(C[m][nt][3] + b2v.y, 0.f);
            o[m][1][0] = fmaf(w3a.x, h0, fmaf(w3a.y, h1, o[m][1][0]));
            o[m][1][1] = fmaf(w3b.x, h0, fmaf(w3b.y, h1, o[m][1][1]));
        }
    }
    #pragma unroll
    for (int m = 0; m < 2; ++m)
        #pragma unroll
        for (int e = 0; e < 2; ++e)
            #pragma unroll
            for (int ch = 0; ch < 2; ++ch) {
                o[m][e][ch] += __shfl_xor_sync(0xffffffffu, o[m][e][ch], 1);
                o[m][e][ch] += __shfl_xor_sync(0xffffffffu, o[m][e][ch], 2);
            }

    if (lm4 == 0) {
        const float bb30 = sF[F_B3 + 0], bb31 = sF[F_B3 + 1];
        #pragma unroll
        for (int m = 0; m < 2; ++m)
            #pragma unroll
            for (int e = 0; e < 2; ++e) {
                const int row = r0 + m * 16 + e * 8;
                const int sl  = row >> 6;
                const int g   = row & 63;
                const int sO  = blockIdx.x * 4 + sl;
                if (g < 63 && sO < Bn) {
                    out[sO * 126 + g]      = o[m][e][0] + bb30;
                    out[sO * 126 + 63 + g] = o[m][e][1] + bb31;
                }
            }
    }
}

extern "C" void kernel_launch(void* const* d_in, const int* in_sizes, int n_in,
                              void* d_out, int out_size) {
    const float* x    = (const float*)d_in[0];
    const int*   adj  = (const int*)  d_in[1];
    const float* ctx  = (const float*)d_in[2];
    const float* gcnW = (const float*)d_in[3];
    const float* gcnB = (const float*)d_in[4];
    const float* ctxW = (const float*)d_in[5];
    const float* ctxB = (const float*)d_in[6];
    const float* W1   = (const float*)d_in[7];
    const float* b1   = (const float*)d_in[8];
    const float* W2   = (const float*)d_in[9];
    const float* b2   = (const float*)d_in[10];
    const float* W3   = (const float*)d_in[11];
    const float* b3   = (const float*)d_in[12];
    float* outp = (float*)d_out;

    prepack_kernel<<<18, 256>>>(W2, ctxW);

    int Bn = in_sizes[0] / 63;
    int grid = (Bn + 3) / 4;
    car_mma10_kernel<<<grid, 256>>>(x, adj, ctx, gcnW, gcnB, ctxB,
                                    W1, b1, b2, W3, b3, outp, Bn);
}

// round 15
// speedup vs baseline: 1.3324x; 1.1126x over previous
#include <cuda_runtime.h>
#include <cuda_fp16.h>
#include <cstdint>

// ============================================================
// Plain fp16 HMMA (A = fp16(h1), B = fp16(W2)): single-term GEMM.
// Error = A-quant + W-quant ~ 2e-4 rel (threshold 1e-3).
// CTA = 256 thr, 4 samples (M=256), warp = 32 rows x 64 cols (2 m-tiles).
// Prepacked W2(fp16) + transposed ctxW.
// ============================================================

#define LDAB 72   // fp16 row stride for B tile (144 B)
#define BPK_U4 (64 * LDAB * 2 / 16)   // 576 uint4 for the single B tile
#define CWT_STRIDE 52                 // floats; conflict-free LDS.128
#define CWT_F4 ((63 * CWT_STRIDE) / 4)  // 819 float4

__device__ uint4  g_Bhi4[BPK_U4];
__device__ float4 g_cwT4[CWT_F4];

__device__ __forceinline__ uint32_t smem_u32(const void* p) {
    uint32_t a;
    asm("{ .reg .u64 t; cvta.to.shared.u64 t, %1; cvt.u32.u64 %0, t; }" : "=r"(a) : "l"(p));
    return a;
}

__device__ __forceinline__ void ldsm4(uint32_t r[4], uint32_t addr) {
    asm volatile("ldmatrix.sync.aligned.m8n8.x4.shared.b16 {%0,%1,%2,%3}, [%4];"
                 : "=r"(r[0]), "=r"(r[1]), "=r"(r[2]), "=r"(r[3]) : "r"(addr));
}

__device__ __forceinline__ void mma16816(float c[4], const uint32_t a[4],
                                          uint32_t b0, uint32_t b1) {
    asm volatile("mma.sync.aligned.m16n8k16.row.col.f32.f16.f16.f32 "
                 "{%0,%1,%2,%3}, {%4,%5,%6,%7}, {%8,%9}, {%0,%1,%2,%3};"
                 : "+f"(c[0]), "+f"(c[1]), "+f"(c[2]), "+f"(c[3])
                 : "r"(a[0]), "r"(a[1]), "r"(a[2]), "r"(a[3]), "r"(b0), "r"(b1));
}

__device__ __forceinline__ uint32_t pack_h2(float a, float b) {
    __half2 h = __floats2half2_rn(a, b);
    return *reinterpret_cast<uint32_t*>(&h);
}

// triu(9) index tables
__constant__ unsigned char c_iu_i[45] = {
    0,0,0,0,0,0,0,0,0, 1,1,1,1,1,1,1,1, 2,2,2,2,2,2,2,
    3,3,3,3,3,3, 4,4,4,4,4, 5,5,5,5, 6,6,6, 7,7, 8};
__constant__ unsigned char c_iu_j[45] = {
    0,1,2,3,4,5,6,7,8, 1,2,3,4,5,6,7,8, 2,3,4,5,6,7,8,
    3,4,5,6,7,8, 4,5,6,7,8, 5,6,7,8, 6,7,8, 7,8, 8};

// float misc region offsets (float4-critical bases % 4 == 0)
#define F_CW   0       // 3276 (63 x 52)
#define F_W1   3276    // 128
#define F_B1   3404    // 64
#define F_B2   3468    // 64
#define F_W3   3532    // 128
#define F_GW   3660    // 49
#define F_GB   3709    // 7
#define F_CB   3716    // 63
#define F_B3   3779    // 2
#define F_X    3784    // 4*63 = 252
#define F_Y    4036    // 252
#define F_ADJ  4288    // 4*81 = 324
#define F_D    4612    // 36
#define F_CTX  4648    // 4*48 = 192 (stride 48, zero padded)
#define F_ZP   4840    // 256
#define F_CP   5096    // 256
#define F_TOTAL 5352

// ---- one-time prepack: W2 -> fp16 [64][72]; ctxW -> transposed [63][52] ----
__global__ void prepack_kernel(const float* __restrict__ W2,
                               const float* __restrict__ ctxW) {
    int i = blockIdx.x * blockDim.x + threadIdx.x;
    if (i < 64 * LDAB) {
        int n = i / LDAB, k = i % LDAB;
        __half hi = __float2half(0.f);
        if (k < 64) hi = __float2half(W2[n * 64 + k]);
        reinterpret_cast<__half*>(g_Bhi4)[i] = hi;
    }
    if (i < 63 * CWT_STRIDE) {
        int g = i / CWT_STRIDE, col = i % CWT_STRIDE;
        reinterpret_cast<float*>(g_cwT4)[i] = (col < 45) ? ctxW[col * 63 + g] : 0.f;
    }
}

__global__ __launch_bounds__(256, 2)
void car_mma11_kernel(const float* __restrict__ x,      // (B,1,9,7)
                      const int*   __restrict__ adj,    // (B,45)
                      const float* __restrict__ ctx,    // (B,1,9,5)
                      const float* __restrict__ gcnW,   // (7,7)
                      const float* __restrict__ gcnB,   // (7,)
                      const float* __restrict__ ctxB,   // (63,)
                      const float* __restrict__ W1,     // (64,2)
                      const float* __restrict__ b1,     // (64,)
                      const float* __restrict__ b2,     // (64,)
                      const float* __restrict__ W3,     // (2,64)
                      const float* __restrict__ b3,     // (2,)
                      float* __restrict__ out,          // (B,2,9,7)
                      int Bn)
{
    __shared__ __align__(16) __half sBhi[64 * LDAB];
    __shared__ __align__(16) float sF[F_TOTAL];

    const int tid  = threadIdx.x;
    const int wid  = tid >> 5;
    const int lane = tid & 31;

    // ---- phase 1: bulk copies of prepacked weights ----
    {
        uint4* dh = reinterpret_cast<uint4*>(sBhi);
        #pragma unroll
        for (int i = tid; i < BPK_U4; i += 256) dh[i] = g_Bhi4[i];
        float4* d4 = reinterpret_cast<float4*>(sF + F_CW);
        for (int i = tid; i < CWT_F4; i += 256) d4[i] = g_cwT4[i];
    }
    if (tid < 32)                  reinterpret_cast<float4*>(sF + F_W1)[tid]      = reinterpret_cast<const float4*>(W1)[tid];
    else if (tid < 64)             reinterpret_cast<float4*>(sF + F_W3)[tid - 32] = reinterpret_cast<const float4*>(W3)[tid - 32];
    else if (tid < 80)             reinterpret_cast<float4*>(sF + F_B1)[tid - 64] = reinterpret_cast<const float4*>(b1)[tid - 64];
    else if (tid < 96)             reinterpret_cast<float4*>(sF + F_B2)[tid - 80] = reinterpret_cast<const float4*>(b2)[tid - 80];
    else if (tid < 96 + 49)        sF[F_GW + tid - 96] = gcnW[tid - 96];
    else if (tid < 145 + 7)        sF[F_GB + tid - 145] = gcnB[tid - 145];
    else if (tid < 152 + 63)       sF[F_CB + tid - 152] = ctxB[tid - 152];
    else if (tid < 215 + 2)        sF[F_B3 + tid - 215] = b3[tid - 215];

    // per-sample staging: 4 samples / CTA
    const int grp = tid >> 6;        // 0..3
    const int g64 = tid & 63;
    const int sG  = blockIdx.x * 4 + grp;
    const bool svalid = (sG < Bn);
    sF[F_ADJ + grp * 81 + g64] = 0.f;
    if (g64 < 17) sF[F_ADJ + grp * 81 + 64 + g64] = 0.f;
    if (g64 < 63) sF[F_X + grp * 63 + g64] = svalid ? x[sG * 63 + g64] : 0.f;
    if (g64 < 48) sF[F_CTX + grp * 48 + g64] =
        (g64 < 45 && svalid) ? ctx[sG * 45 + g64] : 0.f;
    __syncthreads();

    // ---- phase 2: adjacency fill + y = x @ gcnW ----
    if (svalid && g64 < 45) {
        int i = c_iu_i[g64], j = c_iu_j[g64];
        sF[F_ADJ + grp * 81 + i * 9 + j] = (adj[sG * 45 + g64] > 0) ? 1.f : 0.f;
    }
    if (g64 < 63) {
        int n = g64 / 7, f = g64 % 7;
        float acc = 0.f;
        #pragma unroll
        for (int k = 0; k < 7; ++k)
            acc = fmaf(sF[F_X + grp * 63 + n * 7 + k], sF[F_GW + k * 7 + f], acc);
        sF[F_Y + grp * 63 + g64] = acc;
    }
    __syncthreads();

    // ---- phase 3: diag=1, degree norm ----
    if (g64 < 9) {
        sF[F_ADJ + grp * 81 + g64 * 9 + g64] = 1.f;
        float rs = 0.f;
        #pragma unroll
        for (int m = 0; m < 9; ++m) rs += sF[F_ADJ + grp * 81 + g64 * 9 + m];
        sF[F_D + grp * 9 + g64] = rsqrtf(fmaxf(rs, 1.f));
    }
    __syncthreads();

    // ---- phase 4a: per-row zp AND cp (one row per thread, 256 rows) ----
    {
        const int row = tid;
        const int sl  = row >> 6;
        const int g   = row & 63;
        const bool pv = (g < 63) && (blockIdx.x * 4 + sl < Bn);
        float c = 0.f, z = 0.f;
        if (pv) {
            const float* cw = sF + F_CW + g * CWT_STRIDE;
            const float* cx = sF + F_CTX + sl * 48;
            float a0 = 0.f, a1 = 0.f, a2 = 0.f, a3 = 0.f;
            #pragma unroll
            for (int i = 0; i < 12; ++i) {
                const float4 w = *reinterpret_cast<const float4*>(cw + i * 4);
                const float4 v = *reinterpret_cast<const float4*>(cx + i * 4);
                a0 = fmaf(v.x, w.x, a0);
                a1 = fmaf(v.y, w.y, a1);
                a2 = fmaf(v.z, w.z, a2);
                a3 = fmaf(v.w, w.w, a3);
            }
            c = fmaxf(sF[F_CB + g] + ((a0 + a1) + (a2 + a3)), 0.f);

            const int n = g / 7, f = g % 7;
            float acc = 0.f;
            #pragma unroll
            for (int m = 0; m < 9; ++m)
                acc = fmaf(sF[F_ADJ + sl * 81 + n * 9 + m] * sF[F_D + sl * 9 + m],
                           sF[F_Y + sl * 63 + m * 7 + f], acc);
            z = fmaf(acc, sF[F_D + sl * 9 + n], sF[F_GB + f]);
        }
        sF[F_CP + row] = c;
        sF[F_ZP + row] = z;
    }
    __syncthreads();

    // ---- phase 4b: lanes fetch their 4 rows' (zp, cp) ----
    const int l4  = lane >> 2;
    const int lm4 = lane & 3;
    const int r0  = wid * 32 + l4;     // rows r0+8e, e=0..3 (m-tile = e>>1)

    float zp[4], cp[4];
    #pragma unroll
    for (int e = 0; e < 4; ++e) {
        zp[e] = sF[F_ZP + r0 + 8 * e];
        cp[e] = sF[F_CP + r0 + 8 * e];
    }

    // ---- phase 5: k-loop, 2 m-tiles, plain fp16 ----
    float C[2][8][4];
    #pragma unroll
    for (int m = 0; m < 2; ++m)
        #pragma unroll
        for (int n = 0; n < 8; ++n)
            #pragma unroll
            for (int q = 0; q < 4; ++q) C[m][n][q] = 0.f;

    const uint32_t sub = (uint32_t)(lane >> 3);
    const uint32_t j7  = (uint32_t)(lane & 7);
    const uint32_t bOff = ((sub >> 1) * 8 + j7) * (LDAB * 2) + (sub & 1) * 16;
    const uint32_t bHiBase = smem_u32(sBhi) + bOff;

    #pragma unroll
    for (int ks = 0; ks < 4; ++ks) {
        uint32_t Ahi[2][4];
        const int cb = lm4 * 2 + ks * 16;
        #pragma unroll
        for (int p = 0; p < 2; ++p) {
            const int c = cb + p * 8;
            const float4 w4 = *reinterpret_cast<const float4*>(sF + F_W1 + 2 * c);
            const float2 bb = *reinterpret_cast<const float2*>(sF + F_B1 + c);
            #pragma unroll
            for (int m = 0; m < 2; ++m) {
                #pragma unroll
                for (int e = 0; e < 2; ++e) {
                    const int r = 2 * m + e;
                    float v0 = fmaxf(fmaf(zp[r], w4.x, fmaf(cp[r], w4.y, bb.x)), 0.f);
                    float v1 = fmaxf(fmaf(zp[r], w4.z, fmaf(cp[r], w4.w, bb.y)), 0.f);
                    Ahi[m][p * 2 + e] = pack_h2(v0, v1);
                }
            }
        }

        const uint32_t kB = (uint32_t)ks * 32;  // 16 fp16 = 32 bytes
        #pragma unroll
        for (int nh = 0; nh < 2; ++nh) {
            uint32_t bh[2][4];
            ldsm4(bh[0], bHiBase + (uint32_t)(nh * 32)      * (LDAB * 2) + kB);
            ldsm4(bh[1], bHiBase + (uint32_t)(nh * 32 + 16) * (LDAB * 2) + kB);
            #pragma unroll
            for (int t = 0; t < 4; ++t) {
                const int nt = nh * 4 + t;
                const uint32_t b0h = bh[t >> 1][(t & 1) * 2];
                const uint32_t b1h = bh[t >> 1][(t & 1) * 2 + 1];
                #pragma unroll
                for (int m = 0; m < 2; ++m)
                    mma16816(C[m][nt], Ahi[m], b0h, b1h);
            }
        }
    }

    // ---- phase 6: in-register epilogue per m-tile ----
    float o[2][2][2];   // [m][e][ch]
    #pragma unroll
    for (int m = 0; m < 2; ++m)
        #pragma unroll
        for (int e = 0; e < 2; ++e) { o[m][e][0] = 0.f; o[m][e][1] = 0.f; }

    #pragma unroll
    for (int nt = 0; nt < 8; ++nt) {
        const int cc = nt * 8 + lm4 * 2;
        const float2 b2v = *reinterpret_cast<const float2*>(sF + F_B2 + cc);
        const float2 w3a = *reinterpret_cast<const float2*>(sF + F_W3 + cc);
        const float2 w3b = *reinterpret_cast<const float2*>(sF + F_W3 + 64 + cc);
        #pragma unroll
        for (int m = 0; m < 2; ++m) {
            float h0 = fmaxf(C[m][nt][0] + b2v.x, 0.f);
            float h1 = fmaxf(C[m][nt][1] + b2v.y, 0.f);
            o[m][0][0] = fmaf(w3a.x, h0, fmaf(w3a.y, h1, o[m][0][0]));
            o[m][0][1] = fmaf(w3b.x, h0, fmaf(w3b.y, h1, o[m][0][1]));
            h0 = fmaxf(C[m][nt][2] + b2v.x, 0.f);
            h1 = fmaxf(C[m][nt][3] + b2v.y, 0.f);
            o[m][1][0] = fmaf(w3a.x, h0, fmaf(w3a.y, h1, o[m][1][0]));
            o[m][1][1] = fmaf(w3b.x, h0, fmaf(w3b.y, h1, o[m][1][1]));
        }
    }
    #pragma unroll
    for (int m = 0; m < 2; ++m)
        #pragma unroll
        for (int e = 0; e < 2; ++e)
            #pragma unroll
            for (int ch = 0; ch < 2; ++ch) {
                o[m][e][ch] += __shfl_xor_sync(0xffffffffu, o[m][e][ch], 1);
                o[m][e][ch] += __shfl_xor_sync(0xffffffffu, o[m][e][ch], 2);
            }

    if (lm4 == 0) {
        const float bb30 = sF[F_B3 + 0], bb31 = sF[F_B3 + 1];
        #pragma unroll
        for (int m = 0; m < 2; ++m)
            #pragma unroll
            for (int e = 0; e < 2; ++e) {
                const int row = r0 + m * 16 + e * 8;
                const int sl  = row >> 6;
                const int g   = row & 63;
                const int sO  = blockIdx.x * 4 + sl;
                if (g < 63 && sO < Bn) {
                    out[sO * 126 + g]      = o[m][e][0] + bb30;
                    out[sO * 126 + 63 + g] = o[m][e][1] + bb31;
                }
            }
    }
}

extern "C" void kernel_launch(void* const* d_in, const int* in_sizes, int n_in,
                              void* d_out, int out_size) {
    const float* x    = (const float*)d_in[0];
    const int*   adj  = (const int*)  d_in[1];
    const float* ctx  = (const float*)d_in[2];
    const float* gcnW = (const float*)d_in[3];
    const float* gcnB = (const float*)d_in[4];
    const float* ctxW = (const float*)d_in[5];
    const float* ctxB = (const float*)d_in[6];
    const float* W1   = (const float*)d_in[7];
    const float* b1   = (const float*)d_in[8];
    const float* W2   = (const float*)d_in[9];
    const float* b2   = (const float*)d_in[10];
    const float* W3   = (const float*)d_in[11];
    const float* b3   = (const float*)d_in[12];
    float* outp = (float*)d_out;

    prepack_kernel<<<18, 256>>>(W2, ctxW);

    int Bn = in_sizes[0] / 63;
    int grid = (Bn + 3) / 4;
    car_mma11_kernel<<<grid, 256>>>(x, adj, ctx, gcnW, gcnB, ctxB,
                                    W1, b1, b2, W3, b3, outp, Bn);
}

// round 16
// speedup vs baseline: 1.3717x; 1.0295x over previous
#include <cuda_runtime.h>
#include <cuda_fp16.h>
#include <cstdint>

// ============================================================
// Plain fp16 HMMA (A = fp16 h1 computed with HFMA2, B = fp16(W2)).
// CTA = 256 thr, 4 samples (M=256), warp = 32 rows x 64 cols (2 m-tiles).
// Prepacked: W2 fp16 tile, ctxW^T, W1/b1 as separated half arrays.
// ============================================================

#define LDAB 72   // fp16 row stride for B tile (144 B)
#define BPK_U4 (64 * LDAB * 2 / 16)   // 576 uint4 for the single B tile
#define CWT_STRIDE 52                 // floats; conflict-free LDS.128
#define CWT_F4 ((63 * CWT_STRIDE) / 4)  // 819 float4

__device__ uint4  g_Bhi4[BPK_U4];
__device__ float4 g_cwT4[CWT_F4];
__device__ uint4  g_h1pack[24];       // 192 halves: w0[64] | w1[64] | b1[64]

__device__ __forceinline__ uint32_t smem_u32(const void* p) {
    uint32_t a;
    asm("{ .reg .u64 t; cvta.to.shared.u64 t, %1; cvt.u32.u64 %0, t; }" : "=r"(a) : "l"(p));
    return a;
}

__device__ __forceinline__ void ldsm4(uint32_t r[4], uint32_t addr) {
    asm volatile("ldmatrix.sync.aligned.m8n8.x4.shared.b16 {%0,%1,%2,%3}, [%4];"
                 : "=r"(r[0]), "=r"(r[1]), "=r"(r[2]), "=r"(r[3]) : "r"(addr));
}

__device__ __forceinline__ void mma16816(float c[4], const uint32_t a[4],
                                          uint32_t b0, uint32_t b1) {
    asm volatile("mma.sync.aligned.m16n8k16.row.col.f32.f16.f16.f32 "
                 "{%0,%1,%2,%3}, {%4,%5,%6,%7}, {%8,%9}, {%0,%1,%2,%3};"
                 : "+f"(c[0]), "+f"(c[1]), "+f"(c[2]), "+f"(c[3])
                 : "r"(a[0]), "r"(a[1]), "r"(a[2]), "r"(a[3]), "r"(b0), "r"(b1));
}

// triu(9) index tables
__constant__ unsigned char c_iu_i[45] = {
    0,0,0,0,0,0,0,0,0, 1,1,1,1,1,1,1,1, 2,2,2,2,2,2,2,
    3,3,3,3,3,3, 4,4,4,4,4, 5,5,5,5, 6,6,6, 7,7, 8};
__constant__ unsigned char c_iu_j[45] = {
    0,1,2,3,4,5,6,7,8, 1,2,3,4,5,6,7,8, 2,3,4,5,6,7,8,
    3,4,5,6,7,8, 4,5,6,7,8, 5,6,7,8, 6,7,8, 7,8, 8};

// float misc region offsets (float4-critical bases % 4 == 0)
#define F_CW   0       // 3276 (63 x 52)
#define F_B2   3276    // 64
#define F_W3   3340    // 128
#define F_GW   3468    // 49
#define F_GB   3517    // 7
#define F_CB   3524    // 63
#define F_B3   3587    // 2
#define F_X    3592    // 4*63 = 252
#define F_Y    3844    // 252
#define F_ADJ  4096    // 4*81 = 324
#define F_D    4420    // 36
#define F_CTX  4456    // 4*48 = 192 (stride 48, zero padded)
#define F_ZP   4648    // 256
#define F_CP   4904    // 256
#define F_TOTAL 5160

// ---- one-time prepack ----
__global__ void prepack_kernel(const float* __restrict__ W2,
                               const float* __restrict__ ctxW,
                               const float* __restrict__ W1,
                               const float* __restrict__ b1) {
    int i = blockIdx.x * blockDim.x + threadIdx.x;
    if (i < 64 * LDAB) {
        int n = i / LDAB, k = i % LDAB;
        __half hi = __float2half(0.f);
        if (k < 64) hi = __float2half(W2[n * 64 + k]);
        reinterpret_cast<__half*>(g_Bhi4)[i] = hi;
    }
    if (i < 63 * CWT_STRIDE) {
        int g = i / CWT_STRIDE, col = i % CWT_STRIDE;
        reinterpret_cast<float*>(g_cwT4)[i] = (col < 45) ? ctxW[col * 63 + g] : 0.f;
    }
    if (i < 64) {
        __half* h = reinterpret_cast<__half*>(g_h1pack);
        h[i]       = __float2half(W1[2 * i]);       // w0[c]
        h[64 + i]  = __float2half(W1[2 * i + 1]);   // w1[c]
        h[128 + i] = __float2half(b1[i]);           // b[c]
    }
}

__global__ __launch_bounds__(256, 2)
void car_mma12_kernel(const float* __restrict__ x,      // (B,1,9,7)
                      const int*   __restrict__ adj,    // (B,45)
                      const float* __restrict__ ctx,    // (B,1,9,5)
                      const float* __restrict__ gcnW,   // (7,7)
                      const float* __restrict__ gcnB,   // (7,)
                      const float* __restrict__ ctxB,   // (63,)
                      const float* __restrict__ b2,     // (64,)
                      const float* __restrict__ W3,     // (2,64)
                      const float* __restrict__ b3,     // (2,)
                      float* __restrict__ out,          // (B,2,9,7)
                      int Bn)
{
    __shared__ __align__(16) __half sBhi[64 * LDAB];
    __shared__ __align__(16) __half sH1[192];   // w0 | w1 | b1
    __shared__ __align__(16) float sF[F_TOTAL];

    const int tid  = threadIdx.x;
    const int wid  = tid >> 5;
    const int lane = tid & 31;

    // ---- phase 1: bulk copies of prepacked weights ----
    {
        uint4* dh = reinterpret_cast<uint4*>(sBhi);
        #pragma unroll
        for (int i = tid; i < BPK_U4; i += 256) dh[i] = g_Bhi4[i];
        float4* d4 = reinterpret_cast<float4*>(sF + F_CW);
        for (int i = tid; i < CWT_F4; i += 256) d4[i] = g_cwT4[i];
    }
    if (tid < 24)                  reinterpret_cast<uint4*>(sH1)[tid] = g_h1pack[tid];
    else if (tid < 24 + 16)        reinterpret_cast<float4*>(sF + F_B2)[tid - 24] = reinterpret_cast<const float4*>(b2)[tid - 24];
    else if (tid < 40 + 32)        reinterpret_cast<float4*>(sF + F_W3)[tid - 40] = reinterpret_cast<const float4*>(W3)[tid - 40];
    else if (tid < 72 + 49)        sF[F_GW + tid - 72] = gcnW[tid - 72];
    else if (tid < 121 + 7)        sF[F_GB + tid - 121] = gcnB[tid - 121];
    else if (tid < 128 + 63)       sF[F_CB + tid - 128] = ctxB[tid - 128];
    else if (tid < 191 + 2)        sF[F_B3 + tid - 191] = b3[tid - 191];

    // per-sample staging: 4 samples / CTA
    const int grp = tid >> 6;        // 0..3
    const int g64 = tid & 63;
    const int sG  = blockIdx.x * 4 + grp;
    const bool svalid = (sG < Bn);
    sF[F_ADJ + grp * 81 + g64] = 0.f;
    if (g64 < 17) sF[F_ADJ + grp * 81 + 64 + g64] = 0.f;
    if (g64 < 63) sF[F_X + grp * 63 + g64] = svalid ? x[sG * 63 + g64] : 0.f;
    if (g64 < 48) sF[F_CTX + grp * 48 + g64] =
        (g64 < 45 && svalid) ? ctx[sG * 45 + g64] : 0.f;
    __syncthreads();

    // ---- phase 2: adjacency fill + y = x @ gcnW ----
    if (svalid && g64 < 45) {
        int i = c_iu_i[g64], j = c_iu_j[g64];
        sF[F_ADJ + grp * 81 + i * 9 + j] = (adj[sG * 45 + g64] > 0) ? 1.f : 0.f;
    }
    if (g64 < 63) {
        int n = g64 / 7, f = g64 % 7;
        float acc = 0.f;
        #pragma unroll
        for (int k = 0; k < 7; ++k)
            acc = fmaf(sF[F_X + grp * 63 + n * 7 + k], sF[F_GW + k * 7 + f], acc);
        sF[F_Y + grp * 63 + g64] = acc;
    }
    __syncthreads();

    // ---- phase 3: diag=1, degree norm ----
    if (g64 < 9) {
        sF[F_ADJ + grp * 81 + g64 * 9 + g64] = 1.f;
        float rs = 0.f;
        #pragma unroll
        for (int m = 0; m < 9; ++m) rs += sF[F_ADJ + grp * 81 + g64 * 9 + m];
        sF[F_D + grp * 9 + g64] = rsqrtf(fmaxf(rs, 1.f));
    }
    __syncthreads();

    // ---- phase 4a: per-row zp AND cp (one row per thread, 256 rows) ----
    {
        const int row = tid;
        const int sl  = row >> 6;
        const int g   = row & 63;
        const bool pv = (g < 63) && (blockIdx.x * 4 + sl < Bn);
        float c = 0.f, z = 0.f;
        if (pv) {
            const float* cw = sF + F_CW + g * CWT_STRIDE;
            const float* cx = sF + F_CTX + sl * 48;
            float a0 = 0.f, a1 = 0.f, a2 = 0.f, a3 = 0.f;
            #pragma unroll
            for (int i = 0; i < 12; ++i) {
                const float4 w = *reinterpret_cast<const float4*>(cw + i * 4);
                const float4 v = *reinterpret_cast<const float4*>(cx + i * 4);
                a0 = fmaf(v.x, w.x, a0);
                a1 = fmaf(v.y, w.y, a1);
                a2 = fmaf(v.z, w.z, a2);
                a3 = fmaf(v.w, w.w, a3);
            }
            c = fmaxf(sF[F_CB + g] + ((a0 + a1) + (a2 + a3)), 0.f);

            const int n = g / 7, f = g % 7;
            float acc = 0.f;
            #pragma unroll
            for (int m = 0; m < 9; ++m)
                acc = fmaf(sF[F_ADJ + sl * 81 + n * 9 + m] * sF[F_D + sl * 9 + m],
                           sF[F_Y + sl * 63 + m * 7 + f], acc);
            z = fmaf(acc, sF[F_D + sl * 9 + n], sF[F_GB + f]);
        }
        sF[F_CP + row] = c;
        sF[F_ZP + row] = z;
    }
    __syncthreads();

    // ---- phase 4b: lanes fetch their 4 rows' (zp, cp) as broadcast half2 ----
    const int l4  = lane >> 2;
    const int lm4 = lane & 3;
    const int r0  = wid * 32 + l4;     // rows r0+8e, e=0..3 (m-tile = e>>1)

    __half2 zh[4], ch[4];
    #pragma unroll
    for (int e = 0; e < 4; ++e) {
        zh[e] = __float2half2_rn(sF[F_ZP + r0 + 8 * e]);
        ch[e] = __float2half2_rn(sF[F_CP + r0 + 8 * e]);
    }

    // ---- phase 5: k-loop, 2 m-tiles, A built with HFMA2 ----
    float C[2][8][4];
    #pragma unroll
    for (int m = 0; m < 2; ++m)
        #pragma unroll
        for (int n = 0; n < 8; ++n)
            #pragma unroll
            for (int q = 0; q < 4; ++q) C[m][n][q] = 0.f;

    const uint32_t sub = (uint32_t)(lane >> 3);
    const uint32_t j7  = (uint32_t)(lane & 7);
    const uint32_t bOff = ((sub >> 1) * 8 + j7) * (LDAB * 2) + (sub & 1) * 16;
    const uint32_t bHiBase = smem_u32(sBhi) + bOff;
    const __half2 zero2 = __float2half2_rn(0.f);

    #pragma unroll
    for (int ks = 0; ks < 4; ++ks) {
        uint32_t Ahi[2][4];
        const int cb = lm4 * 2 + ks * 16;
        #pragma unroll
        for (int p = 0; p < 2; ++p) {
            const int c = cb + p * 8;          // even channel index
            const __half2 w0 = *reinterpret_cast<const __half2*>(sH1 + c);
            const __half2 w1 = *reinterpret_cast<const __half2*>(sH1 + 64 + c);
            const __half2 bb = *reinterpret_cast<const __half2*>(sH1 + 128 + c);
            #pragma unroll
            for (int m = 0; m < 2; ++m) {
                #pragma unroll
                for (int e = 0; e < 2; ++e) {
                    const int r = 2 * m + e;
                    __half2 v = __hfma2(zh[r], w0, __hfma2(ch[r], w1, bb));
                    v = __hmax2(v, zero2);
                    Ahi[m][p * 2 + e] = *reinterpret_cast<uint32_t*>(&v);
                }
            }
        }

        const uint32_t kB = (uint32_t)ks * 32;  // 16 fp16 = 32 bytes
        #pragma unroll
        for (int nh = 0; nh < 2; ++nh) {
            uint32_t bh[2][4];
            ldsm4(bh[0], bHiBase + (uint32_t)(nh * 32)      * (LDAB * 2) + kB);
            ldsm4(bh[1], bHiBase + (uint32_t)(nh * 32 + 16) * (LDAB * 2) + kB);
            #pragma unroll
            for (int t = 0; t < 4; ++t) {
                const int nt = nh * 4 + t;
                const uint32_t b0h = bh[t >> 1][(t & 1) * 2];
                const uint32_t b1h = bh[t >> 1][(t & 1) * 2 + 1];
                #pragma unroll
                for (int m = 0; m < 2; ++m)
                    mma16816(C[m][nt], Ahi[m], b0h, b1h);
            }
        }
    }

    // ---- phase 6: in-register epilogue per m-tile (fp32) ----
    float o[2][2][2];   // [m][e][ch]
    #pragma unroll
    for (int m = 0; m < 2; ++m)
        #pragma unroll
        for (int e = 0; e < 2; ++e) { o[m][e][0] = 0.f; o[m][e][1] = 0.f; }

    #pragma unroll
    for (int nt = 0; nt < 8; ++nt) {
        const int cc = nt * 8 + lm4 * 2;
        const float2 b2v = *reinterpret_cast<const float2*>(sF + F_B2 + cc);
        const float2 w3a = *reinterpret_cast<const float2*>(sF + F_W3 + cc);
        const float2 w3b = *reinterpret_cast<const float2*>(sF + F_W3 + 64 + cc);
        #pragma unroll
        for (int m = 0; m < 2; ++m) {
            float h0 = fmaxf(C[m][nt][0] + b2v.x, 0.f);
            float h1 = fmaxf(C[m][nt][1] + b2v.y, 0.f);
            o[m][0][0] = fmaf(w3a.x, h0, fmaf(w3a.y, h1, o[m][0][0]));
            o[m][0][1] = fmaf(w3b.x, h0, fmaf(w3b.y, h1, o[m][0][1]));
            h0 = fmaxf(C[m][nt][2] + b2v.x, 0.f);
            h1 = fmaxf(C[m][nt][3] + b2v.y, 0.f);
            o[m][1][0] = fmaf(w3a.x, h0, fmaf(w3a.y, h1, o[m][1][0]));
            o[m][1][1] = fmaf(w3b.x, h0, fmaf(w3b.y, h1, o[m][1][1]));
        }
    }
    #pragma unroll
    for (int m = 0; m < 2; ++m)
        #pragma unroll
        for (int e = 0; e < 2; ++e)
            #pragma unroll
            for (int ch = 0; ch < 2; ++ch) {
                o[m][e][ch] += __shfl_xor_sync(0xffffffffu, o[m][e][ch], 1);
                o[m][e][ch] += __shfl_xor_sync(0xffffffffu, o[m][e][ch], 2);
            }

    if (lm4 == 0) {
        const float bb30 = sF[F_B3 + 0], bb31 = sF[F_B3 + 1];
        #pragma unroll
        for (int m = 0; m < 2; ++m)
            #pragma unroll
            for (int e = 0; e < 2; ++e) {
                const int row = r0 + m * 16 + e * 8;
                const int sl  = row >> 6;
                const int g   = row & 63;
                const int sO  = blockIdx.x * 4 + sl;
                if (g < 63 && sO < Bn) {
                    out[sO * 126 + g]      = o[m][e][0] + bb30;
                    out[sO * 126 + 63 + g] = o[m][e][1] + bb31;
                }
            }
    }
}

extern "C" void kernel_launch(void* const* d_in, const int* in_sizes, int n_in,
                              void* d_out, int out_size) {
    const float* x    = (const float*)d_in[0];
    const int*   adj  = (const int*)  d_in[1];
    const float* ctx  = (const float*)d_in[2];
    const float* gcnW = (const float*)d_in[3];
    const float* gcnB = (const float*)d_in[4];
    const float* ctxW = (const float*)d_in[5];
    const float* ctxB = (const float*)d_in[6];
    const float* W1   = (const float*)d_in[7];
    const float* b1   = (const float*)d_in[8];
    const float* W2   = (const float*)d_in[9];
    const float* b2   = (const float*)d_in[10];
    const float* W3   = (const float*)d_in[11];
    const float* b3   = (const float*)d_in[12];
    float* outp = (float*)d_out;

    prepack_kernel<<<18, 256>>>(W2, ctxW, W1, b1);

    int Bn = in_sizes[0] / 63;
    int grid = (Bn + 3) / 4;
    car_mma12_kernel<<<grid, 256>>>(x, adj, ctx, gcnW, gcnB, ctxB,
                                    b2, W3, b3, outp, Bn);
}

// round 17
// speedup vs baseline: 1.4589x; 1.0635x over previous
#include <cuda_runtime.h>
#include <cuda_fp16.h>
#include <cstdint>

// ============================================================
// fp16 HMMA with FUSED layer-3 MMA:
//   GEMM-1: C = h1 @ W2^T  (C init = b2  -> bias folded)
//   epilogue: A2 = fp16(relu(C))  (C frag layout == A frag layout)
//   GEMM-2: D2 = A2 @ W3pad^T (D2 init = b3; cols 0,1 = out channels)
// CTA = 256 thr, 4 samples (M=256), warp = 32 rows x 64 cols.
// Prepacked: W2 fp16 tile, W3 fp16 8-row tile, ctxW^T, W1/b1 halves.
// ============================================================

#define LDAB 72   // fp16 row stride (144 B)
#define BPK_U4 (64 * LDAB * 2 / 16)   // 576 uint4 for W2 tile
#define B2_U4  (8 * LDAB * 2 / 16)    // 72 uint4 for W3 tile
#define CWT_STRIDE 52
#define CWT_F4 ((63 * CWT_STRIDE) / 4)  // 819 float4

__device__ uint4  g_Bhi4[BPK_U4];
__device__ uint4  g_B2t4[B2_U4];
__device__ float4 g_cwT4[CWT_F4];
__device__ uint4  g_h1pack[24];       // 192 halves: w0[64] | w1[64] | b1[64]

__device__ __forceinline__ uint32_t smem_u32(const void* p) {
    uint32_t a;
    asm("{ .reg .u64 t; cvta.to.shared.u64 t, %1; cvt.u32.u64 %0, t; }" : "=r"(a) : "l"(p));
    return a;
}

__device__ __forceinline__ void ldsm4(uint32_t r[4], uint32_t addr) {
    asm volatile("ldmatrix.sync.aligned.m8n8.x4.shared.b16 {%0,%1,%2,%3}, [%4];"
                 : "=r"(r[0]), "=r"(r[1]), "=r"(r[2]), "=r"(r[3]) : "r"(addr));
}

__device__ __forceinline__ void mma16816(float c[4], const uint32_t a[4],
                                          uint32_t b0, uint32_t b1) {
    asm volatile("mma.sync.aligned.m16n8k16.row.col.f32.f16.f16.f32 "
                 "{%0,%1,%2,%3}, {%4,%5,%6,%7}, {%8,%9}, {%0,%1,%2,%3};"
                 : "+f"(c[0]), "+f"(c[1]), "+f"(c[2]), "+f"(c[3])
                 : "r"(a[0]), "r"(a[1]), "r"(a[2]), "r"(a[3]), "r"(b0), "r"(b1));
}

__device__ __forceinline__ uint32_t pack_h2(float a, float b) {
    __half2 h = __floats2half2_rn(a, b);
    return *reinterpret_cast<uint32_t*>(&h);
}

// triu(9) index tables
__constant__ unsigned char c_iu_i[45] = {
    0,0,0,0,0,0,0,0,0, 1,1,1,1,1,1,1,1, 2,2,2,2,2,2,2,
    3,3,3,3,3,3, 4,4,4,4,4, 5,5,5,5, 6,6,6, 7,7, 8};
__constant__ unsigned char c_iu_j[45] = {
    0,1,2,3,4,5,6,7,8, 1,2,3,4,5,6,7,8, 2,3,4,5,6,7,8,
    3,4,5,6,7,8, 4,5,6,7,8, 5,6,7,8, 6,7,8, 7,8, 8};

// float misc region offsets
#define F_CW   0       // 3276 (63 x 52)
#define F_B2   3276    // 64
#define F_GW   3340    // 49
#define F_GB   3389    // 7
#define F_CB   3396    // 63
#define F_B3   3459    // 2
#define F_X    3464    // 252
#define F_Y    3716    // 252
#define F_ADJ  3968    // 324
#define F_D    4292    // 36
#define F_CTX  4328    // 192
#define F_ZP   4520    // 256
#define F_CP   4776    // 256
#define F_TOTAL 5032

// ---- one-time prepack ----
__global__ void prepack_kernel(const float* __restrict__ W2,
                               const float* __restrict__ ctxW,
                               const float* __restrict__ W1,
                               const float* __restrict__ b1,
                               const float* __restrict__ W3) {
    int i = blockIdx.x * blockDim.x + threadIdx.x;
    if (i < 64 * LDAB) {
        int n = i / LDAB, k = i % LDAB;
        __half hi = __float2half(0.f);
        if (k < 64) hi = __float2half(W2[n * 64 + k]);
        reinterpret_cast<__half*>(g_Bhi4)[i] = hi;
    }
    if (i < 8 * LDAB) {   // W3 tile: rows 0,1 = W3 channels; rows 2-7 zero
        int n = i / LDAB, k = i % LDAB;
        __half hv = __float2half(0.f);
        if (n < 2 && k < 64) hv = __float2half(W3[n * 64 + k]);
        reinterpret_cast<__half*>(g_B2t4)[i] = hv;
    }
    if (i < 63 * CWT_STRIDE) {
        int g = i / CWT_STRIDE, col = i % CWT_STRIDE;
        reinterpret_cast<float*>(g_cwT4)[i] = (col < 45) ? ctxW[col * 63 + g] : 0.f;
    }
    if (i < 64) {
        __half* h = reinterpret_cast<__half*>(g_h1pack);
        h[i]       = __float2half(W1[2 * i]);
        h[64 + i]  = __float2half(W1[2 * i + 1]);
        h[128 + i] = __float2half(b1[i]);
    }
}

__global__ __launch_bounds__(256, 2)
void car_mma13_kernel(const float* __restrict__ x,      // (B,1,9,7)
                      const int*   __restrict__ adj,    // (B,45)
                      const float* __restrict__ ctx,    // (B,1,9,5)
                      const float* __restrict__ gcnW,   // (7,7)
                      const float* __restrict__ gcnB,   // (7,)
                      const float* __restrict__ ctxB,   // (63,)
                      const float* __restrict__ b2,     // (64,)
                      const float* __restrict__ b3,     // (2,)
                      float* __restrict__ out,          // (B,2,9,7)
                      int Bn)
{
    __shared__ __align__(16) __half sBhi[64 * LDAB];
    __shared__ __align__(16) __half sB2[8 * LDAB];
    __shared__ __align__(16) __half sH1[192];   // w0 | w1 | b1
    __shared__ __align__(16) float sF[F_TOTAL];

    const int tid  = threadIdx.x;
    const int wid  = tid >> 5;
    const int lane = tid & 31;

    // ---- phase 1: bulk copies of prepacked weights ----
    {
        uint4* dh = reinterpret_cast<uint4*>(sBhi);
        #pragma unroll
        for (int i = tid; i < BPK_U4; i += 256) dh[i] = g_Bhi4[i];
        float4* d4 = reinterpret_cast<float4*>(sF + F_CW);
        for (int i = tid; i < CWT_F4; i += 256) d4[i] = g_cwT4[i];
    }
    if (tid < 72)                  reinterpret_cast<uint4*>(sB2)[tid] = g_B2t4[tid];
    else if (tid < 72 + 24)        reinterpret_cast<uint4*>(sH1)[tid - 72] = g_h1pack[tid - 72];
    else if (tid < 96 + 16)        reinterpret_cast<float4*>(sF + F_B2)[tid - 96] = reinterpret_cast<const float4*>(b2)[tid - 96];
    else if (tid < 112 + 49)       sF[F_GW + tid - 112] = gcnW[tid - 112];
    else if (tid < 161 + 7)        sF[F_GB + tid - 161] = gcnB[tid - 161];
    else if (tid < 168 + 63)       sF[F_CB + tid - 168] = ctxB[tid - 168];
    else if (tid < 231 + 2)        sF[F_B3 + tid - 231] = b3[tid - 231];

    // per-sample staging: 4 samples / CTA
    const int grp = tid >> 6;        // 0..3
    const int g64 = tid & 63;
    const int sG  = blockIdx.x * 4 + grp;
    const bool svalid = (sG < Bn);
    sF[F_ADJ + grp * 81 + g64] = 0.f;
    if (g64 < 17) sF[F_ADJ + grp * 81 + 64 + g64] = 0.f;
    if (g64 < 63) sF[F_X + grp * 63 + g64] = svalid ? x[sG * 63 + g64] : 0.f;
    if (g64 < 48) sF[F_CTX + grp * 48 + g64] =
        (g64 < 45 && svalid) ? ctx[sG * 45 + g64] : 0.f;
    __syncthreads();

    // ---- phase 2: adjacency fill + y = x @ gcnW ----
    if (svalid && g64 < 45) {
        int i = c_iu_i[g64], j = c_iu_j[g64];
        sF[F_ADJ + grp * 81 + i * 9 + j] = (adj[sG * 45 + g64] > 0) ? 1.f : 0.f;
    }
    if (g64 < 63) {
        int n = g64 / 7, f = g64 % 7;
        float acc = 0.f;
        #pragma unroll
        for (int k = 0; k < 7; ++k)
            acc = fmaf(sF[F_X + grp * 63 + n * 7 + k], sF[F_GW + k * 7 + f], acc);
        sF[F_Y + grp * 63 + g64] = acc;
    }
    __syncthreads();

    // ---- phase 3: diag=1, degree norm ----
    if (g64 < 9) {
        sF[F_ADJ + grp * 81 + g64 * 9 + g64] = 1.f;
        float rs = 0.f;
        #pragma unroll
        for (int m = 0; m < 9; ++m) rs += sF[F_ADJ + grp * 81 + g64 * 9 + m];
        sF[F_D + grp * 9 + g64] = rsqrtf(fmaxf(rs, 1.f));
    }
    __syncthreads();

    // ---- phase 4a: per-row zp AND cp (one row per thread, 256 rows) ----
    {
        const int row = tid;
        const int sl  = row >> 6;
        const int g   = row & 63;
        const bool pv = (g < 63) && (blockIdx.x * 4 + sl < Bn);
        float c = 0.f, z = 0.f;
        if (pv) {
            const float* cw = sF + F_CW + g * CWT_STRIDE;
            const float* cx = sF + F_CTX + sl * 48;
            float a0 = 0.f, a1 = 0.f, a2 = 0.f, a3 = 0.f;
            #pragma unroll
            for (int i = 0; i < 12; ++i) {
                const float4 w = *reinterpret_cast<const float4*>(cw + i * 4);
                const float4 v = *reinterpret_cast<const float4*>(cx + i * 4);
                a0 = fmaf(v.x, w.x, a0);
                a1 = fmaf(v.y, w.y, a1);
                a2 = fmaf(v.z, w.z, a2);
                a3 = fmaf(v.w, w.w, a3);
            }
            c = fmaxf(sF[F_CB + g] + ((a0 + a1) + (a2 + a3)), 0.f);

            const int n = g / 7, f = g % 7;
            float acc = 0.f;
            #pragma unroll
            for (int m = 0; m < 9; ++m)
                acc = fmaf(sF[F_ADJ + sl * 81 + n * 9 + m] * sF[F_D + sl * 9 + m],
                           sF[F_Y + sl * 63 + m * 7 + f], acc);
            z = fmaf(acc, sF[F_D + sl * 9 + n], sF[F_GB + f]);
        }
        sF[F_CP + row] = c;
        sF[F_ZP + row] = z;
    }
    __syncthreads();

    // ---- phase 4b: lanes fetch their 4 rows' (zp, cp) as broadcast half2 ----
    const int l4  = lane >> 2;
    const int lm4 = lane & 3;
    const int r0  = wid * 32 + l4;

    __half2 zh[4], ch[4];
    #pragma unroll
    for (int e = 0; e < 4; ++e) {
        zh[e] = __float2half2_rn(sF[F_ZP + r0 + 8 * e]);
        ch[e] = __float2half2_rn(sF[F_CP + r0 + 8 * e]);
    }

    // ---- phase 5: k-loop; C initialized to b2 (bias folded) ----
    float C[2][8][4];
    #pragma unroll
    for (int nt = 0; nt < 8; ++nt) {
        const float2 b2v = *reinterpret_cast<const float2*>(sF + F_B2 + nt * 8 + lm4 * 2);
        #pragma unroll
        for (int m = 0; m < 2; ++m) {
            C[m][nt][0] = b2v.x; C[m][nt][1] = b2v.y;
            C[m][nt][2] = b2v.x; C[m][nt][3] = b2v.y;
        }
    }

    const uint32_t sub = (uint32_t)(lane >> 3);
    const uint32_t j7  = (uint32_t)(lane & 7);
    const uint32_t bOff = ((sub >> 1) * 8 + j7) * (LDAB * 2) + (sub & 1) * 16;
    const uint32_t bHiBase = smem_u32(sBhi) + bOff;
    const __half2 zero2 = __float2half2_rn(0.f);

    #pragma unroll
    for (int ks = 0; ks < 4; ++ks) {
        uint32_t Ahi[2][4];
        const int cb = lm4 * 2 + ks * 16;
        #pragma unroll
        for (int p = 0; p < 2; ++p) {
            const int c = cb + p * 8;
            const __half2 w0 = *reinterpret_cast<const __half2*>(sH1 + c);
            const __half2 w1 = *reinterpret_cast<const __half2*>(sH1 + 64 + c);
            const __half2 bb = *reinterpret_cast<const __half2*>(sH1 + 128 + c);
            #pragma unroll
            for (int m = 0; m < 2; ++m) {
                #pragma unroll
                for (int e = 0; e < 2; ++e) {
                    const int r = 2 * m + e;
                    __half2 v = __hfma2(zh[r], w0, __hfma2(ch[r], w1, bb));
                    v = __hmax2(v, zero2);
                    Ahi[m][p * 2 + e] = *reinterpret_cast<uint32_t*>(&v);
                }
            }
        }

        const uint32_t kB = (uint32_t)ks * 32;
        #pragma unroll
        for (int nh = 0; nh < 2; ++nh) {
            uint32_t bh[2][4];
            ldsm4(bh[0], bHiBase + (uint32_t)(nh * 32)      * (LDAB * 2) + kB);
            ldsm4(bh[1], bHiBase + (uint32_t)(nh * 32 + 16) * (LDAB * 2) + kB);
            #pragma unroll
            for (int t = 0; t < 4; ++t) {
                const int nt = nh * 4 + t;
                const uint32_t b0h = bh[t >> 1][(t & 1) * 2];
                const uint32_t b1h = bh[t >> 1][(t & 1) * 2 + 1];
                #pragma unroll
                for (int m = 0; m < 2; ++m)
                    mma16816(C[m][nt], Ahi[m], b0h, b1h);
            }
        }
    }

    // ---- phase 6: fused layer-3 MMA; D2 init = b3 (cols 0,1 only) ----
    float D2[2][4];
    {
        const float bb30 = (lm4 == 0) ? sF[F_B3 + 0] : 0.f;
        const float bb31 = (lm4 == 0) ? sF[F_B3 + 1] : 0.f;
        #pragma unroll
        for (int m = 0; m < 2; ++m) {
            D2[m][0] = bb30; D2[m][1] = bb31;
            D2[m][2] = bb30; D2[m][3] = bb31;
        }
    }

    {
        const __half* b2row = sB2 + l4 * LDAB + lm4 * 2;
        #pragma unroll
        for (int ks = 0; ks < 4; ++ks) {
            const uint32_t b0 = *reinterpret_cast<const uint32_t*>(b2row + ks * 16);
            const uint32_t b1 = *reinterpret_cast<const uint32_t*>(b2row + ks * 16 + 8);
            #pragma unroll
            for (int m = 0; m < 2; ++m) {
                uint32_t A2[4];
                A2[0] = pack_h2(fmaxf(C[m][2 * ks][0], 0.f),     fmaxf(C[m][2 * ks][1], 0.f));
                A2[1] = pack_h2(fmaxf(C[m][2 * ks][2], 0.f),     fmaxf(C[m][2 * ks][3], 0.f));
                A2[2] = pack_h2(fmaxf(C[m][2 * ks + 1][0], 0.f), fmaxf(C[m][2 * ks + 1][1], 0.f));
                A2[3] = pack_h2(fmaxf(C[m][2 * ks + 1][2], 0.f), fmaxf(C[m][2 * ks + 1][3], 0.f));
                mma16816(D2[m], A2, b0, b1);
            }
        }
    }

    // ---- phase 7: store (lm4==0 lanes hold output channels 0,1) ----
    if (lm4 == 0) {
        #pragma unroll
        for (int m = 0; m < 2; ++m)
            #pragma unroll
            for (int e = 0; e < 2; ++e) {
                const int row = r0 + m * 16 + e * 8;
                const int sl  = row >> 6;
                const int g   = row & 63;
                const int sO  = blockIdx.x * 4 + sl;
                if (g < 63 && sO < Bn) {
                    out[sO * 126 + g]      = D2[m][e * 2 + 0];
                    out[sO * 126 + 63 + g] = D2[m][e * 2 + 1];
                }
            }
    }
}

extern "C" void kernel_launch(void* const* d_in, const int* in_sizes, int n_in,
                              void* d_out, int out_size) {
    const float* x    = (const float*)d_in[0];
    const int*   adj  = (const int*)  d_in[1];
    const float* ctx  = (const float*)d_in[2];
    const float* gcnW = (const float*)d_in[3];
    const float* gcnB = (const float*)d_in[4];
    const float* ctxW = (const float*)d_in[5];
    const float* ctxB = (const float*)d_in[6];
    const float* W1   = (const float*)d_in[7];
    const float* b1   = (const float*)d_in[8];
    const float* W2   = (const float*)d_in[9];
    const float* b2   = (const float*)d_in[10];
    const float* W3   = (const float*)d_in[11];
    const float* b3   = (const float*)d_in[12];
    float* outp = (float*)d_out;

    prepack_kernel<<<18, 256>>>(W2, ctxW, W1, b1, W3);

    int Bn = in_sizes[0] / 63;
    int grid = (Bn + 3) / 4;
    car_mma13_kernel<<<grid, 256>>>(x, adj, ctx, gcnW, gcnB, ctxB,
                                    b2, b3, outp, Bn);
}